// round 7
// baseline (speedup 1.0000x reference)
#include <cuda_runtime.h>

#define NCTA 128
#define NTHR 256
#define SW   2052                      // W row stride (floats)
#define SA   132                       // A row stride (floats)
#define ABUF (64 * SA)
#define A_OFF (16 * SW)
#define BIAS_OFF (A_OFF + 2 * ABUF)
#define SMEM_FLOATS (BIAS_OFF + 16)    // 49744 floats = 198976 B
#define HNOFF (512 * 64 * 1024)

__device__ float g_h1[2][64 * 1024];
__device__ float g_h2[2][64 * 1024];
__device__ unsigned g_cnt, g_gen;

__device__ __forceinline__ unsigned su32(const void* p) {
    return (unsigned)__cvta_generic_to_shared(p);
}
#define CP16(d, s) asm volatile("cp.async.cg.shared.global [%0],[%1],16;" :: "r"(d), "l"(s))
#define CPCOMMIT() asm volatile("cp.async.commit_group;")
#define FMA2(c, a, b) asm("fma.rn.f32x2 %0,%1,%2,%0;" : "+l"(c) : "l"(a), "l"(b))
#define LDS2U64(lo, hi, ad) \
    asm volatile("ld.shared.v2.u64 {%0,%1},[%2];" : "=l"(lo), "=l"(hi) : "r"(ad))

union UF { unsigned long long u; float2 f; };

__device__ __forceinline__ float fast_tanh(float v) {
    float e = __expf(2.0f * v);
    return 1.0f - __fdividef(2.0f, e + 1.0f);
}

__device__ __forceinline__ void gsync() {
    __syncthreads();
    if (threadIdx.x == 0) {
        __threadfence();
        volatile unsigned* vg = &g_gen;
        volatile unsigned* vc = &g_cnt;
        unsigned g = *vg;
        if (atomicAdd(&g_cnt, 1u) == NCTA - 1) {
            *vc = 0u;
            __threadfence();
            *vg = g + 1u;
        } else {
            while (*vg == g) {}
            __threadfence();
        }
    }
    __syncthreads();
}

// stage one [64 m][128 k] activation chunk into A buffer `buf` via cp.async
__device__ __forceinline__ void stage(float* sm, int buf, const float* inp,
                                      const float* hp, int c) {
    const float* base = (c < 8) ? inp + c * 128 : hp + (c - 8) * 128;
    unsigned d0 = su32(sm) + (unsigned)(A_OFF + buf * ABUF) * 4u;
    int tid = threadIdx.x;
#pragma unroll
    for (int r = 0; r < 8; r++) {
        int idx = r * NTHR + tid;
        int m = idx >> 5, q = idx & 31;
        CP16(d0 + (unsigned)(m * SA + q * 4) * 4u, base + (size_t)m * 1024 + q * 4);
    }
    CPCOMMIT();
}

__global__ void rnn_init(const float* __restrict__ h0) {
    int i = blockIdx.x * blockDim.x + threadIdx.x;
    const int n = 64 * 1024;
    for (int idx = i; idx < n; idx += gridDim.x * blockDim.x) {
        g_h1[1][idx] = h0[idx];         // h1[t=-1] in buf 1
        g_h2[1][idx] = h0[n + idx];     // h2[t=-1] in buf 1
    }
    if (i == 0) { g_cnt = 0u; g_gen = 0u; }
}

__global__ void __launch_bounds__(NTHR, 1) rnn_main(
    const float* __restrict__ x,
    const float* __restrict__ Wx, const float* __restrict__ bx,
    const float* __restrict__ Wh, const float* __restrict__ bh,
    float* __restrict__ out, int out_size)
{
    extern __shared__ float sm[];
    const int tid = threadIdx.x, cta = blockIdx.x;
    const int layer = cta >> 6, col0 = (cta & 63) * 16;

    // ---- load fused [16 j][2048 k] weight slice into SMEM once ----
    {
        const float* wxl = Wx + (size_t)layer * 1024 * 1024;
        const float* whl = Wh + (size_t)layer * 1024 * 1024;
        unsigned wb = su32(sm);
#pragma unroll 4
        for (int r = 0; r < 32; r++) {
            int idx = r * NTHR + tid;
            int j = idx >> 9;
            int k4 = (idx & 511) * 4;
            const float* src = (k4 < 1024)
                ? wxl + (size_t)(col0 + j) * 1024 + k4
                : whl + (size_t)(col0 + j) * 1024 + (k4 - 1024);
            CP16(wb + (unsigned)(j * SW + k4) * 4u, src);
        }
        CPCOMMIT();
        if (tid < 16)
            sm[BIAS_OFF + tid] = bx[layer * 1024 + col0 + tid]
                               + bh[layer * 1024 + col0 + tid];
        asm volatile("cp.async.wait_group 0;");
        __syncthreads();
    }

    const int wid = tid >> 5, lane = tid & 31;
    const int mg = lane >> 2, jq = lane & 3;
    const bool wr_hn = out_size >= HNOFF + 2 * 64 * 1024;
    const unsigned abase0 = su32(sm) + (unsigned)A_OFF * 4u
                          + (unsigned)(mg * SA + wid * 16) * 4u;
    const unsigned wbase = su32(sm) + (unsigned)(jq * SW + wid * 16) * 4u;

    for (int p = 0; p <= 512; p++) {
        const bool act = (layer == 0) ? (p < 512) : (p >= 1);
        if (act) {
            const int t = (layer == 0) ? p : p - 1;
            const float* inp = (layer == 0) ? x + (size_t)t * 65536 : g_h1[t & 1];
            const float* hp  = (layer == 0) ? g_h1[(p + 1) & 1] : g_h2[(t + 1) & 1];
            float* hout      = (layer == 0) ? g_h1[p & 1] : g_h2[t & 1];

            unsigned long long acc[8][4];
#pragma unroll
            for (int i = 0; i < 8; i++)
#pragma unroll
                for (int jj = 0; jj < 4; jj++) acc[i][jj] = 0ull;

            stage(sm, 0, inp, hp, 0);

            for (int c = 0; c < 16; c++) {
                if (c < 15) {
                    stage(sm, (c + 1) & 1, inp, hp, c + 1);
                    asm volatile("cp.async.wait_group 1;");
                } else {
                    asm volatile("cp.async.wait_group 0;");
                }
                __syncthreads();
                const unsigned ab  = abase0 + (unsigned)((c & 1) * ABUF) * 4u;
                const unsigned wbc = wbase + (unsigned)(c * 128) * 4u;
#pragma unroll
                for (int s = 0; s < 4; s++) {
                    unsigned long long a[8][2], w[4][2];
#pragma unroll
                    for (int i = 0; i < 8; i++)
                        LDS2U64(a[i][0], a[i][1], ab + s * 16 + i * (8 * SA * 4));
#pragma unroll
                    for (int jj = 0; jj < 4; jj++)
                        LDS2U64(w[jj][0], w[jj][1], wbc + s * 16 + jj * (4 * SW * 4));
#pragma unroll
                    for (int i = 0; i < 8; i++)
#pragma unroll
                        for (int jj = 0; jj < 4; jj++) {
                            FMA2(acc[i][jj], a[i][0], w[jj][0]);
                            FMA2(acc[i][jj], a[i][1], w[jj][1]);
                        }
                }
                __syncthreads();
            }

            // ---- cross-warp K reduction (reuse A region) ----
            float* red = sm + A_OFF;
#pragma unroll
            for (int i = 0; i < 8; i++)
#pragma unroll
                for (int jj = 0; jj < 4; jj++) {
                    UF u; u.u = acc[i][jj];
                    red[wid * 1024 + (mg + 8 * i) * 16 + (jq + 4 * jj)] = u.f.x + u.f.y;
                }
            __syncthreads();
            {
                const int m = tid >> 2, jg = tid & 3;
                float4 s4 = make_float4(0.f, 0.f, 0.f, 0.f);
#pragma unroll
                for (int w2 = 0; w2 < 8; w2++) {
                    float4 v = *(const float4*)&red[w2 * 1024 + m * 16 + jg * 4];
                    s4.x += v.x; s4.y += v.y; s4.z += v.z; s4.w += v.w;
                }
                float4 b4 = *(const float4*)&sm[BIAS_OFF + jg * 4];
                float4 h4;
                h4.x = fast_tanh(s4.x + b4.x);
                h4.y = fast_tanh(s4.y + b4.y);
                h4.z = fast_tanh(s4.z + b4.z);
                h4.w = fast_tanh(s4.w + b4.w);
                *(float4*)&hout[m * 1024 + col0 + jg * 4] = h4;
                if (layer == 1) {
                    float4 o4 = make_float4(10.f * h4.x, 10.f * h4.y,
                                            10.f * h4.z, 10.f * h4.w);
                    *(float4*)&out[(size_t)t * 65536 + m * 1024 + col0 + jg * 4] = o4;
                }
                if (wr_hn && t == 511)
                    *(float4*)&out[HNOFF + (size_t)layer * 65536
                                   + m * 1024 + col0 + jg * 4] = h4;
            }
        }
        gsync();
    }
}

extern "C" void kernel_launch(void* const* d_in, const int* in_sizes, int n_in,
                              void* d_out, int out_size) {
    const float* x  = (const float*)d_in[0];
    const float* h0 = (const float*)d_in[1];
    const float* Wx = (const float*)d_in[2];
    const float* bx = (const float*)d_in[3];
    const float* Wh = (const float*)d_in[4];
    const float* bh = (const float*)d_in[5];
    (void)in_sizes; (void)n_in;

    cudaFuncSetAttribute(rnn_main, cudaFuncAttributeMaxDynamicSharedMemorySize,
                         SMEM_FLOATS * 4);
    rnn_init<<<64, 256>>>(h0);
    rnn_main<<<NCTA, NTHR, SMEM_FLOATS * 4>>>(x, Wx, bx, Wh, bh,
                                              (float*)d_out, out_size);
}